// round 9
// baseline (speedup 1.0000x reference)
#include <cuda_runtime.h>
#include <cstdint>

#define NIMG 4
#define PBINS 10
#define LBINS 6
#define NBINS 66                      // 60 inter bins + 6 label-count bins
#define TPB 256
#define NWARPS (TPB/32)               // 8
#define NHIST (NWARPS*2)              // 16 half-warp histograms
#define BLOCKS_PER_IMG 148            // 592 blocks total = exactly 4 per SM
#define TOTAL_BLOCKS (BLOCKS_PER_IMG * NIMG)
#define VECS_PER_IMG (1024*1024/4)    // 262144 float4 per image
#define STRIDE (BLOCKS_PER_IMG * TPB) // 37888
#define KITERS 7                      // 7*37888 >= 262144 (last iter partial)

// Global scratch (zero-initialized at module load; kernel restores zeros
// before exit so every graph replay sees identical state).
__device__ float g_bins[NIMG][NBINS];
__device__ unsigned int g_ticket;

__global__ void __launch_bounds__(TPB, 4)
sc_fused_kernel(const float* __restrict__ pred,
                const int* __restrict__ pconn,
                const int* __restrict__ lconn,
                float* __restrict__ out) {
    // Per-HALF-WARP shared histograms (4 KB): even/odd lanes use separate
    // 64-slot arrays, halving the ATOMS address-conflict degree.
    __shared__ float whist[NHIST][64];
    __shared__ float scnt[LBINS];
    __shared__ float losses[NIMG];
    __shared__ float binc[NIMG][NBINS];
    __shared__ bool  s_last;

    const int tid  = threadIdx.x;
    const int lane = tid & 31;
    const int wid  = tid >> 5;
    const int img  = blockIdx.y;

    #pragma unroll
    for (int k = tid; k < NHIST * 64; k += TPB) ((float*)whist)[k] = 0.0f;
    if (tid < LBINS) scnt[tid] = 0.0f;
    __syncthreads();

    const size_t base = (size_t)img * VECS_PER_IMG;
    const float4* __restrict__ p4  = ((const float4*)pred)  + base;
    const int4*   __restrict__ pc4 = ((const int4*)pconn)   + base;
    const int4*   __restrict__ lc4 = ((const int4*)lconn)   + base;

    float* const myhist = whist[wid * 2 + (lane & 1)];

    // Label counts: 6 byte-fields packed in a 64-bit register.
    // <= 28 pixels/thread -> fields never overflow 8 bits.
    unsigned long long cnt = 0ULL;

    // Software pipeline: prefetch iter k+1's 3 vectors before processing k,
    // so LDGs stay outstanding while the ATOMS burst drains.
    int v = blockIdx.x * TPB + tid;
    bool val = (v < VECS_PER_IMG);                  // true for k<6 always
    int vc = val ? v : 0;
    float4 P = p4[vc];
    int4   C = pc4[vc];
    int4   L = lc4[vc];

    #pragma unroll
    for (int k = 0; k < KITERS; k++) {
        float4 Pn; int4 Cn, Ln; bool valn = false;
        if (k < KITERS - 1) {
            int vn = v + STRIDE;
            valn = (vn < VECS_PER_IMG);
            int vcn = valn ? vn : 0;
            Pn = p4[vcn];
            Cn = pc4[vcn];
            Ln = lc4[vcn];
        }
        if (val) {
            atomicAdd(&myhist[L.x * PBINS + C.x], P.x);
            atomicAdd(&myhist[L.y * PBINS + C.y], P.y);
            atomicAdd(&myhist[L.z * PBINS + C.z], P.z);
            atomicAdd(&myhist[L.w * PBINS + C.w], P.w);
            cnt += (1ULL << (8 * L.x)) + (1ULL << (8 * L.y))
                 + (1ULL << (8 * L.z)) + (1ULL << (8 * L.w));
        }
        P = Pn; C = Cn; L = Ln; val = valn;
        v += STRIDE;
    }

    // Warp-reduce packed counts. Split 8-bit fields into two words of
    // 16-bit-spaced fields so sums over 32 lanes (<=896) don't overflow.
    unsigned long long lo = cnt & 0x00FF00FF00FF00FFULL;         // labels 0,2,4
    unsigned long long hi = (cnt >> 8) & 0x00FF00FF00FF00FFULL;  // labels 1,3,5
    #pragma unroll
    for (int d = 16; d > 0; d >>= 1) {
        lo += __shfl_down_sync(0xFFFFFFFFu, lo, d);
        hi += __shfl_down_sync(0xFFFFFFFFu, hi, d);
    }
    if (lane == 0) {
        #pragma unroll
        for (int l = 0; l < 3; l++) {
            atomicAdd(&scnt[2 * l],     (float)((lo >> (16 * l)) & 0xFFFFULL));
            atomicAdd(&scnt[2 * l + 1], (float)((hi >> (16 * l)) & 0xFFFFULL));
        }
    }
    __syncthreads();

    // Fold 16 half-warp histograms + counts into global bins.
    if (tid < 60) {
        float t = 0.0f;
        #pragma unroll
        for (int w = 0; w < NHIST; w++) t += whist[w][tid];
        atomicAdd(&g_bins[img][tid], t);
    } else if (tid < NBINS) {
        atomicAdd(&g_bins[img][tid], scnt[tid - 60]);
    }

    // ---- last-block-done: finalize inline, then restore scratch to zero ----
    if (tid == 0) {
        __threadfence();
        unsigned int tk = atomicAdd(&g_ticket, 1u);
        s_last = (tk == TOTAL_BLOCKS - 1);
    }
    __syncthreads();
    if (!s_last) return;

    // All blocks' atomics visible (threadfence-before-ticket). Read via L2.
    if (tid < NIMG * NBINS)
        ((float*)binc)[tid] = __ldcg(&((const float*)g_bins)[tid]);
    {
        int k = tid + TPB;
        if (k < NIMG * NBINS)
            ((float*)binc)[k] = __ldcg(&((const float*)g_bins)[k]);
    }
    __syncthreads();

    if (tid < NIMG) {
        const float* b = binc[tid];

        // pred_area[p] = sum_l inter[l][p]
        float pa[PBINS];
        #pragma unroll
        for (int p = 0; p < PBINS; p++) {
            float sum = 0.0f;
            #pragma unroll
            for (int l = 0; l < LBINS; l++) sum += b[l * PBINS + p];
            pa[p] = sum;
        }

        bool colnz[PBINS];
        #pragma unroll
        for (int p = 0; p < PBINS; p++) colnz[p] = false;

        float pair_conn_sum = 0.0f;
        #pragma unroll
        for (int l = 1; l < LBINS; l++) {
            float la = b[60 + l];
            float pc = 0.0f;
            int   pn = 0;
            #pragma unroll
            for (int p = 1; p < PBINS; p++) {
                float in = b[l * PBINS + p];
                if (in != 0.0f) {
                    float uni = la + pa[p] - in;
                    pc += in / uni;
                    pn++;
                    colnz[p] = true;
                }
            }
            if (pn > 0) pair_conn_sum += pc / (float)pn;
        }

        int lone = 0;
        #pragma unroll
        for (int p = 1; p < PBINS; p++) if (!colnz[p]) lone++;

        float denom = (float)(LBINS - 1) + (float)lone;
        losses[tid] = 1.0f - pair_conn_sum / denom;
    }
    __syncthreads();

    if (tid == 0)
        out[0] = (losses[0] + losses[1] + losses[2] + losses[3]) * 0.25f;

    // Restore scratch to zero for the next (graph-replayed) call.
    if (tid < NIMG * NBINS) ((float*)g_bins)[tid] = 0.0f;
    {
        int k = tid + TPB;
        if (k < NIMG * NBINS) ((float*)g_bins)[k] = 0.0f;
    }
    if (tid == 0) g_ticket = 0u;
}

extern "C" void kernel_launch(void* const* d_in, const int* in_sizes, int n_in,
                              void* d_out, int out_size) {
    const float* pred  = (const float*)d_in[0];
    const int*   pconn = (const int*)d_in[1];
    const int*   lconn = (const int*)d_in[2];
    float* out = (float*)d_out;

    dim3 grid(BLOCKS_PER_IMG, NIMG);
    sc_fused_kernel<<<grid, TPB>>>(pred, pconn, lconn, out);
}

// round 10
// speedup vs baseline: 1.0381x; 1.0381x over previous
#include <cuda_runtime.h>
#include <cstdint>

#define NIMG 4
#define PBINS 10
#define LBINS 6
#define NBINS 66                      // 60 inter bins + 6 label-count bins
#define ROWS 64                       // 60 real + 3 dummy (60,61,62) + 1 pad
#define TPB 256
#define NWARPS (TPB/32)               // 8
#define BLOCKS_PER_IMG 111            // 444 blocks = exactly 3 per SM, balanced
#define TOTAL_BLOCKS (BLOCKS_PER_IMG * NIMG)
#define VECS_PER_IMG (1024*1024/4)    // 262144 float4 per image
#define STRIDE (BLOCKS_PER_IMG * TPB) // 28416
#define KITERS 10                     // 10*28416 >= 262144 (guarded)
#define SMEM_BYTES (ROWS * TPB * 4)   // 65536 -> dynamic smem

// Global scratch (zero-initialized at module load; kernel restores zeros
// before exit so every graph replay sees identical state).
__device__ float g_bins[NIMG][NBINS];
__device__ unsigned int g_ticket;

__global__ void __launch_bounds__(TPB, 3)
sc_fused_kernel(const float* __restrict__ pred,
                const int* __restrict__ pconn,
                const int* __restrict__ lconn,
                float* __restrict__ out) {
    // Per-thread private histogram columns: s[row*TPB + tid].
    // Row stride = 1024B (multiple of 128B) -> bank = tid%32, conflict-free.
    // NO atomics anywhere in the hot loop (ATOMS @2cyc/lane was the wall).
    extern __shared__ float s[];               // [ROWS][TPB] = 64 KB
    __shared__ float s_part[NBINS][NWARPS];
    __shared__ float losses[NIMG];
    __shared__ float binc[NIMG][NBINS];
    __shared__ bool  s_last;

    const int tid  = threadIdx.x;
    const int lane = tid & 31;
    const int wid  = tid >> 5;
    const int img  = blockIdx.y;

    #pragma unroll
    for (int b = 0; b < ROWS; b++) s[b * TPB + tid] = 0.0f;
    __syncthreads();

    const size_t base = (size_t)img * VECS_PER_IMG;
    const float4* __restrict__ p4  = ((const float4*)pred)  + base;
    const int4*   __restrict__ pc4 = ((const int4*)pconn)   + base;
    const int4*   __restrict__ lc4 = ((const int4*)lconn)   + base;

    // Label counts: 6 byte-fields packed in a 64-bit register.
    // <= 40 pixels/thread -> fields never overflow 8 bits.
    unsigned long long cnt = 0ULL;

    // Software pipeline: prefetch iter k+1's 3 vectors before processing k.
    int v = blockIdx.x * TPB + tid;
    bool val = (v < VECS_PER_IMG);
    int vc = val ? v : 0;
    float4 P = p4[vc];
    int4   C = pc4[vc];
    int4   L = lc4[vc];

    #pragma unroll
    for (int k = 0; k < KITERS; k++) {
        float4 Pn; int4 Cn, Ln; bool valn = false;
        if (k < KITERS - 1) {
            int vn = v + STRIDE;
            valn = (vn < VECS_PER_IMG);
            int vcn = valn ? vn : 0;
            Pn = p4[vcn];
            Cn = pc4[vcn];
            Ln = lc4[vcn];
        }
        if (val) {
            int b0 = L.x * PBINS + C.x;
            int b1 = L.y * PBINS + C.y;
            int b2 = L.z * PBINS + C.z;
            int b3 = L.w * PBINS + C.w;
            float v0 = P.x, v1 = P.y, v2 = P.z, v3 = P.w;

            // Merge duplicate bins among the 4 components; redirect dups to
            // distinct dummy rows so the 4 RMW addresses are provably
            // disjoint -> 4 independent LDS / 4 STS, one chain per iter.
            if (b1 == b0) { v0 += v1; b1 = 60; }
            if (b2 == b0) { v0 += v2; b2 = 61; }
            else if (b2 == b1) { v1 += v2; b2 = 61; }
            if (b3 == b0) { v0 += v3; b3 = 62; }
            else if (b3 == b1) { v1 += v3; b3 = 62; }
            else if (b3 == b2) { v2 += v3; b3 = 62; }

            float h0 = s[b0 * TPB + tid];
            float h1 = s[b1 * TPB + tid];
            float h2 = s[b2 * TPB + tid];
            float h3 = s[b3 * TPB + tid];
            s[b0 * TPB + tid] = h0 + v0;
            s[b1 * TPB + tid] = h1 + v1;
            s[b2 * TPB + tid] = h2 + v2;
            s[b3 * TPB + tid] = h3 + v3;

            cnt += (1ULL << (8 * L.x)) + (1ULL << (8 * L.y))
                 + (1ULL << (8 * L.z)) + (1ULL << (8 * L.w));
        }
        P = Pn; C = Cn; L = Ln; val = valn;
        v += STRIDE;
    }
    __syncthreads();

    // Reduce 256 private columns per bin: warp shuffle, then 8 partials.
    // Counts: split 8-bit fields into 16-bit-spaced halves (sum<=1280 ok).
    unsigned long long lo = cnt & 0x00FF00FF00FF00FFULL;         // labels 0,2,4
    unsigned long long hi = (cnt >> 8) & 0x00FF00FF00FF00FFULL;  // labels 1,3,5
    #pragma unroll
    for (int b = 0; b < NBINS; b++) {
        float x;
        if (b < 60) x = s[b * TPB + tid];     // bank = tid%32, conflict-free
        else {
            int l = b - 60;
            unsigned long long w = (l & 1) ? hi : lo;
            x = (float)((w >> (16 * (l >> 1))) & 0xFFFFULL);
        }
        x += __shfl_down_sync(0xFFFFFFFFu, x, 16);
        x += __shfl_down_sync(0xFFFFFFFFu, x, 8);
        x += __shfl_down_sync(0xFFFFFFFFu, x, 4);
        x += __shfl_down_sync(0xFFFFFFFFu, x, 2);
        x += __shfl_down_sync(0xFFFFFFFFu, x, 1);
        if (lane == 0) s_part[b][wid] = x;
    }
    __syncthreads();

    if (tid < NBINS) {
        float t = 0.0f;
        #pragma unroll
        for (int w = 0; w < NWARPS; w++) t += s_part[tid][w];
        atomicAdd(&g_bins[img][tid], t);
    }

    // ---- last-block-done: finalize inline, then restore scratch to zero ----
    if (tid == 0) {
        __threadfence();
        unsigned int tk = atomicAdd(&g_ticket, 1u);
        s_last = (tk == TOTAL_BLOCKS - 1);
    }
    __syncthreads();
    if (!s_last) return;

    // All blocks' atomics visible (threadfence-before-ticket). Read via L2.
    if (tid < NIMG * NBINS)
        ((float*)binc)[tid] = __ldcg(&((const float*)g_bins)[tid]);
    {
        int k = tid + TPB;
        if (k < NIMG * NBINS)
            ((float*)binc)[k] = __ldcg(&((const float*)g_bins)[k]);
    }
    __syncthreads();

    if (tid < NIMG) {
        const float* b = binc[tid];

        // pred_area[p] = sum_l inter[l][p]
        float pa[PBINS];
        #pragma unroll
        for (int p = 0; p < PBINS; p++) {
            float sum = 0.0f;
            #pragma unroll
            for (int l = 0; l < LBINS; l++) sum += b[l * PBINS + p];
            pa[p] = sum;
        }

        bool colnz[PBINS];
        #pragma unroll
        for (int p = 0; p < PBINS; p++) colnz[p] = false;

        float pair_conn_sum = 0.0f;
        #pragma unroll
        for (int l = 1; l < LBINS; l++) {
            float la = b[60 + l];
            float pc = 0.0f;
            int   pn = 0;
            #pragma unroll
            for (int p = 1; p < PBINS; p++) {
                float in = b[l * PBINS + p];
                if (in != 0.0f) {
                    float uni = la + pa[p] - in;
                    pc += in / uni;
                    pn++;
                    colnz[p] = true;
                }
            }
            if (pn > 0) pair_conn_sum += pc / (float)pn;
        }

        int lone = 0;
        #pragma unroll
        for (int p = 1; p < PBINS; p++) if (!colnz[p]) lone++;

        float denom = (float)(LBINS - 1) + (float)lone;
        losses[tid] = 1.0f - pair_conn_sum / denom;
    }
    __syncthreads();

    if (tid == 0)
        out[0] = (losses[0] + losses[1] + losses[2] + losses[3]) * 0.25f;

    // Restore scratch to zero for the next (graph-replayed) call.
    if (tid < NIMG * NBINS) ((float*)g_bins)[tid] = 0.0f;
    {
        int k = tid + TPB;
        if (k < NIMG * NBINS) ((float*)g_bins)[k] = 0.0f;
    }
    if (tid == 0) g_ticket = 0u;
}

extern "C" void kernel_launch(void* const* d_in, const int* in_sizes, int n_in,
                              void* d_out, int out_size) {
    const float* pred  = (const float*)d_in[0];
    const int*   pconn = (const int*)d_in[1];
    const int*   lconn = (const int*)d_in[2];
    float* out = (float*)d_out;

    cudaFuncSetAttribute(sc_fused_kernel,
                         cudaFuncAttributeMaxDynamicSharedMemorySize, SMEM_BYTES);

    dim3 grid(BLOCKS_PER_IMG, NIMG);
    sc_fused_kernel<<<grid, TPB, SMEM_BYTES>>>(pred, pconn, lconn, out);
}

// round 11
// speedup vs baseline: 1.5205x; 1.4647x over previous
#include <cuda_runtime.h>
#include <cstdint>

#define NIMG 4
#define PBINS 10
#define LBINS 6
#define NBINS 66                      // 60 inter bins + 6 label-count bins
#define TPB 192
#define NWARPS (TPB/32)               // 6
#define BLOCKS_PER_IMG 148            // 592 blocks = exactly 4 per SM
#define TOTAL_BLOCKS (BLOCKS_PER_IMG * NIMG)
#define VECS_PER_IMG (1024*1024/4)    // 262144 float4 per image
#define STRIDE (BLOCKS_PER_IMG * TPB) // 28416
#define KITERS 10                     // 10*28416 = 284160 >= 262144 (guarded)
#define GROUPS (KITERS/2)             // 5 double-vec batches

// Global scratch (zero-initialized at module load; kernel restores zeros
// before exit so every graph replay sees identical state).
__device__ float g_bins[NIMG][NBINS];
__device__ unsigned int g_ticket;

__global__ void __launch_bounds__(TPB, 4)
sc_fused_kernel(const float* __restrict__ pred,
                const int* __restrict__ pconn,
                const int* __restrict__ lconn,
                float* __restrict__ out) {
    // Per-WARP shared histograms (1.5 KB). 768 thr/SM -> 85 regs/thread:
    // enough to keep a 6-LDG.128 double-buffered batch genuinely in flight.
    __shared__ float whist[NWARPS][64];
    __shared__ float scnt[LBINS];
    __shared__ float losses[NIMG];
    __shared__ float binc[NIMG][NBINS];
    __shared__ bool  s_last;

    const int tid  = threadIdx.x;
    const int lane = tid & 31;
    const int wid  = tid >> 5;
    const int img  = blockIdx.y;

    #pragma unroll
    for (int k = tid; k < NWARPS * 64; k += TPB) ((float*)whist)[k] = 0.0f;
    if (tid < LBINS) scnt[tid] = 0.0f;
    __syncthreads();

    const size_t base = (size_t)img * VECS_PER_IMG;
    const float4* __restrict__ p4  = ((const float4*)pred)  + base;
    const int4*   __restrict__ pc4 = ((const int4*)pconn)   + base;
    const int4*   __restrict__ lc4 = ((const int4*)lconn)   + base;

    float* const myhist = whist[wid];

    // Label counts: 6 byte-fields packed in a 64-bit register.
    // <= 40 pixels/thread -> fields never overflow 8 bits.
    unsigned long long cnt = 0ULL;

    // Double-buffered batches of 2 vecs: 6 LDG.128 outstanding while the
    // previous batch's ATOMS burst drains.
    int v = blockIdx.x * TPB + tid;

    bool a0v = (v < VECS_PER_IMG);
    bool a1v = (v + STRIDE < VECS_PER_IMG);
    int  i0 = a0v ? v : 0;
    int  i1 = a1v ? v + STRIDE : 0;
    float4 P0 = p4[i0], P1 = p4[i1];
    int4   C0 = pc4[i0], C1 = pc4[i1];
    int4   L0 = lc4[i0], L1 = lc4[i1];

    #pragma unroll
    for (int g = 0; g < GROUPS; g++) {
        float4 Q0, Q1; int4 D0, D1, M0, M1;
        bool b0v = false, b1v = false;
        if (g < GROUPS - 1) {
            int w0 = v + 2 * STRIDE;
            int w1 = v + 3 * STRIDE;
            b0v = (w0 < VECS_PER_IMG);
            b1v = (w1 < VECS_PER_IMG);
            int j0 = b0v ? w0 : 0;
            int j1 = b1v ? w1 : 0;
            Q0 = p4[j0]; D0 = pc4[j0]; M0 = lc4[j0];
            Q1 = p4[j1]; D1 = pc4[j1]; M1 = lc4[j1];
        }

        if (a0v) {
            atomicAdd(&myhist[L0.x * PBINS + C0.x], P0.x);
            atomicAdd(&myhist[L0.y * PBINS + C0.y], P0.y);
            atomicAdd(&myhist[L0.z * PBINS + C0.z], P0.z);
            atomicAdd(&myhist[L0.w * PBINS + C0.w], P0.w);
            cnt += (1ULL << (8 * L0.x)) + (1ULL << (8 * L0.y))
                 + (1ULL << (8 * L0.z)) + (1ULL << (8 * L0.w));
        }
        if (a1v) {
            atomicAdd(&myhist[L1.x * PBINS + C1.x], P1.x);
            atomicAdd(&myhist[L1.y * PBINS + C1.y], P1.y);
            atomicAdd(&myhist[L1.z * PBINS + C1.z], P1.z);
            atomicAdd(&myhist[L1.w * PBINS + C1.w], P1.w);
            cnt += (1ULL << (8 * L1.x)) + (1ULL << (8 * L1.y))
                 + (1ULL << (8 * L1.z)) + (1ULL << (8 * L1.w));
        }

        P0 = Q0; C0 = D0; L0 = M0; a0v = b0v;
        P1 = Q1; C1 = D1; L1 = M1; a1v = b1v;
        v += 2 * STRIDE;
    }

    // Warp-reduce packed counts. Split 8-bit fields into two words of
    // 16-bit-spaced fields so sums over 32 lanes (<=1280) don't overflow.
    unsigned long long lo = cnt & 0x00FF00FF00FF00FFULL;         // labels 0,2,4
    unsigned long long hi = (cnt >> 8) & 0x00FF00FF00FF00FFULL;  // labels 1,3,5
    #pragma unroll
    for (int d = 16; d > 0; d >>= 1) {
        lo += __shfl_down_sync(0xFFFFFFFFu, lo, d);
        hi += __shfl_down_sync(0xFFFFFFFFu, hi, d);
    }
    if (lane == 0) {
        #pragma unroll
        for (int l = 0; l < 3; l++) {
            atomicAdd(&scnt[2 * l],     (float)((lo >> (16 * l)) & 0xFFFFULL));
            atomicAdd(&scnt[2 * l + 1], (float)((hi >> (16 * l)) & 0xFFFFULL));
        }
    }
    __syncthreads();

    // Fold 6 warp-histograms + counts into global bins.
    if (tid < 60) {
        float t = 0.0f;
        #pragma unroll
        for (int w = 0; w < NWARPS; w++) t += whist[w][tid];
        atomicAdd(&g_bins[img][tid], t);
    } else if (tid < NBINS) {
        atomicAdd(&g_bins[img][tid], scnt[tid - 60]);
    }

    // ---- last-block-done: finalize inline, then restore scratch to zero ----
    if (tid == 0) {
        __threadfence();
        unsigned int tk = atomicAdd(&g_ticket, 1u);
        s_last = (tk == TOTAL_BLOCKS - 1);
    }
    __syncthreads();
    if (!s_last) return;

    // All blocks' atomics visible (threadfence-before-ticket). Read via L2.
    #pragma unroll
    for (int c = 0; c < 2; c++) {
        int k = tid + c * TPB;
        if (k < NIMG * NBINS)
            ((float*)binc)[k] = __ldcg(&((const float*)g_bins)[k]);
    }
    __syncthreads();

    if (tid < NIMG) {
        const float* b = binc[tid];

        // pred_area[p] = sum_l inter[l][p]
        float pa[PBINS];
        #pragma unroll
        for (int p = 0; p < PBINS; p++) {
            float sum = 0.0f;
            #pragma unroll
            for (int l = 0; l < LBINS; l++) sum += b[l * PBINS + p];
            pa[p] = sum;
        }

        bool colnz[PBINS];
        #pragma unroll
        for (int p = 0; p < PBINS; p++) colnz[p] = false;

        float pair_conn_sum = 0.0f;
        #pragma unroll
        for (int l = 1; l < LBINS; l++) {
            float la = b[60 + l];
            float pc = 0.0f;
            int   pn = 0;
            #pragma unroll
            for (int p = 1; p < PBINS; p++) {
                float in = b[l * PBINS + p];
                if (in != 0.0f) {
                    float uni = la + pa[p] - in;
                    pc += in / uni;
                    pn++;
                    colnz[p] = true;
                }
            }
            if (pn > 0) pair_conn_sum += pc / (float)pn;
        }

        int lone = 0;
        #pragma unroll
        for (int p = 1; p < PBINS; p++) if (!colnz[p]) lone++;

        float denom = (float)(LBINS - 1) + (float)lone;
        losses[tid] = 1.0f - pair_conn_sum / denom;
    }
    __syncthreads();

    if (tid == 0)
        out[0] = (losses[0] + losses[1] + losses[2] + losses[3]) * 0.25f;

    // Restore scratch to zero for the next (graph-replayed) call.
    #pragma unroll
    for (int c = 0; c < 2; c++) {
        int k = tid + c * TPB;
        if (k < NIMG * NBINS) ((float*)g_bins)[k] = 0.0f;
    }
    if (tid == 0) g_ticket = 0u;
}

extern "C" void kernel_launch(void* const* d_in, const int* in_sizes, int n_in,
                              void* d_out, int out_size) {
    const float* pred  = (const float*)d_in[0];
    const int*   pconn = (const int*)d_in[1];
    const int*   lconn = (const int*)d_in[2];
    float* out = (float*)d_out;

    dim3 grid(BLOCKS_PER_IMG, NIMG);
    sc_fused_kernel<<<grid, TPB>>>(pred, pconn, lconn, out);
}